// round 12
// baseline (speedup 1.0000x reference)
#include <cuda_runtime.h>
#include <math.h>

#define BATCH 16
#define CH    3
#define H     512
#define W     512
#define WS    11

#define TX    64
#define TY    32
#define TXW   (TX + 10)     // 74 plane columns
#define XPAD  80            // padded x iteration range for scalar pass V
#define XP2   40            // padded x-pair iteration range (38 real pairs)
#define PITCH 75            // odd pitch -> conflict-free LDS
#define NTHREADS 256
#define NBLK  ((W/TX)*(H/TY)*BATCH)   // 2048

typedef unsigned long long u64;

#define W0 0.00102838f
#define W1 0.00759876f
#define W2 0.03600077f
#define W3 0.10936070f
#define W4 0.21300554f
#define W5 0.26601173f
__device__ __forceinline__ float gwc(int k) {
    const float t[WS] = {W0,W1,W2,W3,W4,W5,W4,W3,W2,W1,W0};
    return t[k];   // fully-unrolled callers -> compile-time constant
}

__device__ float    g_pnum[NBLK];
__device__ float    g_pden[NBLK];
__device__ unsigned g_cnt;

// ---------------- f32x2 packed helpers ----------------
__device__ __forceinline__ u64 pk2(float lo, float hi) {
    u64 r; asm("mov.b64 %0, {%1, %2};" : "=l"(r) : "f"(lo), "f"(hi)); return r;
}
__device__ __forceinline__ float lo2(u64 v) {
    float a, b; asm("mov.b64 {%0, %1}, %2;" : "=f"(a), "=f"(b) : "l"(v)); return a;
}
__device__ __forceinline__ float hi2(u64 v) {
    float a, b; asm("mov.b64 {%0, %1}, %2;" : "=f"(a), "=f"(b) : "l"(v)); return b;
}
__device__ __forceinline__ u64 fma2(u64 a, u64 b, u64 c) {
    u64 d; asm("fma.rn.f32x2 %0, %1, %2, %3;" : "=l"(d) : "l"(a), "l"(b), "l"(c)); return d;
}

extern __shared__ float smem[];

// smem layout:
//   MQ : TY*PITCH ulonglong2 = 38.4KB
//        .x = (mu1v, mu2v)  packed vertical means
//        .y = (Esumv, E12v) packed vertical (E11+E22, E12)
//   (mask phase reuses this plane as float scratch)
#define SMEM_FLOATS (TY*PITCH*4)
#define SMEM_BYTES  (SMEM_FLOATS * (int)sizeof(float))

// ---------------- pass V: vertical box filter on match (mask scratch) ---------
template<bool CHK>
__device__ __forceinline__ void mask_passV(const float* __restrict__ mp,
                                           int x0, int y0, float* scr, int tid) {
    for (int i = tid; i < XPAD * (TY / 4); i += NTHREADS) {
        int x  = i % XPAD;
        int yb = (i / XPAD) * 4;
        if (x >= TXW) continue;
        int gx = x0 + x - 5;
        float S[4] = {0, 0, 0, 0};
        if (CHK) {
            bool xin = (unsigned)gx < W;
            #pragma unroll
            for (int k = 0; k < WS + 3; k++) {
                int gy = y0 + yb + k - 5;
                float v = (xin && (unsigned)gy < H) ? mp[gy * W + gx] : 0.f;
                #pragma unroll
                for (int r = 0; r < 4; r++) {
                    int kk = k - r;
                    if (kk >= 0 && kk < WS) S[r] += v;
                }
            }
        } else {
            const float* col = mp + (size_t)(y0 + yb - 5) * W + gx;
            #pragma unroll
            for (int k = 0; k < WS + 3; k++) {
                float v = col[k * W];
                #pragma unroll
                for (int r = 0; r < 4; r++) {
                    int kk = k - r;
                    if (kk >= 0 && kk < WS) S[r] += v;
                }
            }
        }
        #pragma unroll
        for (int r = 0; r < 4; r++) scr[(yb + r) * PITCH + x] = S[r];
    }
}

// ---------------- pass V (edge blocks): scalar, bounds-checked -----------------
__device__ __forceinline__ void chan_passV_edge(const float* __restrict__ p1,
                                                const float* __restrict__ p2,
                                                int x0, int y0,
                                                ulonglong2* MQ, int tid) {
    for (int i = tid; i < XPAD * (TY / 4); i += NTHREADS) {
        int x  = i % XPAD;
        int yb = (i / XPAD) * 4;
        if (x >= TXW) continue;
        int gx = x0 + x - 5;
        bool xin = (unsigned)gx < W;

        u64 VM[4] = {0,0,0,0};
        u64 VQ[4] = {0,0,0,0};

        #pragma unroll
        for (int k = 0; k < WS + 3; k++) {
            int gy = y0 + yb + k - 5;
            bool in = xin && (unsigned)gy < H;
            float a  = in ? p1[gy * W + gx] : 0.f;
            float bb = in ? p2[gy * W + gx] : 0.f;
            u64 v = pk2(a, bb);
            u64 q = pk2(fmaf(bb, bb, a * a), a * bb);
            #pragma unroll
            for (int r = 0; r < 4; r++) {
                int kk = k - r;
                if (kk >= 0 && kk < WS) {
                    float w = gwc(kk);
                    u64 ww = pk2(w, w);
                    VM[r] = fma2(ww, v, VM[r]);
                    VQ[r] = fma2(ww, q, VQ[r]);
                }
            }
        }
        #pragma unroll
        for (int r = 0; r < 4; r++) {
            MQ[(yb + r) * PITCH + x] = make_ulonglong2(VM[r], VQ[r]);
        }
    }
}

// ---------------- pass V (interior blocks): x-paired float2 loads --------------
// Pair xp covers plane columns (2*xp-1, 2*xp); gx base = x0-6+2*xp is even ->
// 8B-aligned LDG.64, halving LDG instruction count at equal bytes.
__device__ __forceinline__ void chan_passV_int(const float* __restrict__ p1,
                                               const float* __restrict__ p2,
                                               int x0, int y0,
                                               ulonglong2* MQ, int tid) {
    for (int i = tid; i < XP2 * (TY / 4); i += NTHREADS) {
        int xp = i % XP2;
        int yb = (i / XP2) * 4;
        if (xp >= 38) continue;
        int gx = x0 - 6 + 2 * xp;
        const float2* c1 = (const float2*)(p1 + (size_t)(y0 + yb - 5) * W + gx);
        const float2* c2 = (const float2*)(p2 + (size_t)(y0 + yb - 5) * W + gx);

        u64 VM0[4] = {0,0,0,0}, VQ0[4] = {0,0,0,0};
        u64 VM1[4] = {0,0,0,0}, VQ1[4] = {0,0,0,0};

        #pragma unroll
        for (int k = 0; k < WS + 3; k++) {
            float2 a = c1[k * (W / 2)];
            float2 b = c2[k * (W / 2)];
            u64 v0 = pk2(a.x, b.x);
            u64 v1 = pk2(a.y, b.y);
            u64 q0 = pk2(fmaf(b.x, b.x, a.x * a.x), a.x * b.x);
            u64 q1 = pk2(fmaf(b.y, b.y, a.y * a.y), a.y * b.y);
            #pragma unroll
            for (int r = 0; r < 4; r++) {
                int kk = k - r;
                if (kk >= 0 && kk < WS) {
                    float w = gwc(kk);
                    u64 ww = pk2(w, w);
                    VM0[r] = fma2(ww, v0, VM0[r]);
                    VQ0[r] = fma2(ww, q0, VQ0[r]);
                    VM1[r] = fma2(ww, v1, VM1[r]);
                    VQ1[r] = fma2(ww, q1, VQ1[r]);
                }
            }
        }
        int xL = 2 * xp - 1;
        #pragma unroll
        for (int r = 0; r < 4; r++) {
            int o = (yb + r) * PITCH;
            if (xp > 0)  MQ[o + xL]     = make_ulonglong2(VM0[r], VQ0[r]);
            if (xp < 37) MQ[o + xL + 1] = make_ulonglong2(VM1[r], VQ1[r]);
        }
    }
}

__global__ __launch_bounds__(NTHREADS, 4) void ssim_kernel(
    const float* __restrict__ img1,
    const float* __restrict__ img2,
    const float* __restrict__ match,
    float* __restrict__ out)
{
    ulonglong2* MQ  = (ulonglong2*)smem;
    float*      scr = smem;           // mask scratch aliases the MQ plane

    const int tid = threadIdx.x;
    const int x0 = blockIdx.x * TX;
    const int y0 = blockIdx.y * TY;
    const int b  = blockIdx.z;
    const bool interior = (x0 > 0) && (x0 + TX < W) && (y0 > 0) && (y0 + TY < H);

    float lnum = 0.f;
    float lden = 0.f;
    float msk[2][4];

    // =================== mask phase (scratch in MQ plane) ===================
    {
        const float* mp = match + (size_t)b * H * W;
        if (interior) mask_passV<false>(mp, x0, y0, scr, tid);
        else          mask_passV<true >(mp, x0, y0, scr, tid);
        __syncthreads();
        #pragma unroll
        for (int ii = 0; ii < 2; ii++) {
            int i  = tid + ii * NTHREADS;
            int y  = i & 31;
            int xg = i >> 5;
            int base = y * PITCH + 4 * xg;
            float tb[WS + 3];
            #pragma unroll
            for (int k = 0; k < WS + 3; k++) tb[k] = scr[base + k];
            float S = 0.f;
            #pragma unroll
            for (int k = 0; k < WS; k++) S += tb[k];
            #pragma unroll
            for (int r = 0; r < 4; r++) {
                if (r > 0) S = S - tb[r - 1] + tb[r + WS - 1];
                float m = S * (1.0f / 121.0f) + 1e-07f;
                float mv = (m > 0.5f) ? (1.0f + 1e-07f) : 1e-07f;
                msk[ii][r] = mv;
                lden += mv;
            }
        }
        __syncthreads();
    }

    // =================== per-channel: pass V then pass H ===================
    for (int c = 0; c < CH; c++) {
        const float* p1 = img1 + ((size_t)b * CH + c) * H * W;
        const float* p2 = img2 + ((size_t)b * CH + c) * H * W;

        if (interior) chan_passV_int (p1, p2, x0, y0, MQ, tid);
        else          chan_passV_edge(p1, p2, x0, y0, MQ, tid);
        __syncthreads();

        // ---- pass H: horizontal Gaussian + SSIM. lanes = y (conflict-free)
        #pragma unroll
        for (int ii = 0; ii < 2; ii++) {
            int i  = tid + ii * NTHREADS;
            int y  = i & 31;
            int xg = i >> 5;
            int base = y * PITCH + 4 * xg;

            u64 HM[4] = {0,0,0,0};
            u64 HQ[4] = {0,0,0,0};
            #pragma unroll
            for (int k = 0; k < WS + 3; k++) {
                ulonglong2 mq = MQ[base + k];      // one LDS.128
                u64 mk = mq.x;
                u64 qk = mq.y;
                #pragma unroll
                for (int r = 0; r < 4; r++) {
                    int kk = k - r;
                    if (kk >= 0 && kk < WS) {
                        float w = gwc(kk);
                        u64 ww = pk2(w, w);
                        HM[r] = fma2(ww, mk, HM[r]);
                        HQ[r] = fma2(ww, qk, HQ[r]);
                    }
                }
            }
            const float C1 = 1e-4f;
            const float C2 = 9e-4f;
            #pragma unroll
            for (int r = 0; r < 4; r++) {
                float mu1  = lo2(HM[r]);
                float mu2  = hi2(HM[r]);
                float esum = lo2(HQ[r]);
                float e12  = hi2(HQ[r]);
                float mu1sq = mu1 * mu1;
                float mu2sq = mu2 * mu2;
                float mu12  = mu1 * mu2;
                float sden = esum - mu1sq - mu2sq;   // s11 + s22
                float s12  = e12 - mu12;
                float numer = (2.f * mu12 + C1) * (2.f * s12 + C2);
                float denom = (mu1sq + mu2sq + C1) * (sden + C2);
                float ssim = __fdividef(numer, denom);
                lnum += (1.f - ssim) * msk[ii][r];
            }
        }
        __syncthreads();
    }

    // =================== block reduction + partials + last-block finalize ========
    const unsigned full = 0xffffffffu;
    #pragma unroll
    for (int o = 16; o > 0; o >>= 1) {
        lnum += __shfl_down_sync(full, lnum, o);
        lden += __shfl_down_sync(full, lden, o);
    }
    __shared__ float red[16];
    __shared__ unsigned s_last;
    int wid = tid >> 5, lane = tid & 31;
    if (lane == 0) { red[wid] = lnum; red[wid + 8] = lden; }
    __syncthreads();
    if (tid == 0) {
        float n = 0.f, d = 0.f;
        #pragma unroll
        for (int i = 0; i < 8; i++) { n += red[i]; d += red[i + 8]; }
        int blk = (blockIdx.z * gridDim.y + blockIdx.y) * gridDim.x + blockIdx.x;
        g_pnum[blk] = n;
        g_pden[blk] = d;
        __threadfence();
        unsigned o = atomicAdd(&g_cnt, 1u);
        s_last = (o == NBLK - 1) ? 1u : 0u;
    }
    __syncthreads();

    if (s_last) {
        __threadfence();
        double dn = 0.0, dd = 0.0;
        for (int i = tid; i < NBLK; i += NTHREADS) {
            dn += (double)g_pnum[i];
            dd += (double)g_pden[i];
        }
        #pragma unroll
        for (int o = 16; o > 0; o >>= 1) {
            dn += __shfl_down_sync(full, dn, o);
            dd += __shfl_down_sync(full, dd, o);
        }
        __shared__ double dred[16];
        if (lane == 0) { dred[wid] = dn; dred[wid + 8] = dd; }
        __syncthreads();
        if (tid == 0) {
            double n = 0.0, d = 0.0;
            #pragma unroll
            for (int i = 0; i < 8; i++) { n += dred[i]; d += dred[i + 8]; }
            out[0] = (float)(n / d / 3.0);
            g_cnt = 0;   // reset for next graph replay
        }
    }
}

extern "C" void kernel_launch(void* const* d_in, const int* in_sizes, int n_in,
                              void* d_out, int out_size) {
    const float* img1  = (const float*)d_in[0];
    const float* img2  = (const float*)d_in[1];
    const float* match = (const float*)d_in[2];

    cudaFuncSetAttribute(ssim_kernel,
                         cudaFuncAttributeMaxDynamicSharedMemorySize, SMEM_BYTES);

    dim3 grid(W / TX, H / TY, BATCH);
    ssim_kernel<<<grid, NTHREADS, SMEM_BYTES>>>(img1, img2, match, (float*)d_out);
}

// round 13
// speedup vs baseline: 1.0194x; 1.0194x over previous
#include <cuda_runtime.h>
#include <math.h>

#define BATCH 16
#define CH    3
#define H     512
#define W     512
#define WS    11

#define TX    64
#define TY    32
#define TXW   (TX + 10)     // 74 plane columns
#define XPAD  80            // padded x iteration range for pass V
#define PITCH 75            // odd pitch -> conflict-free LDS
#define NTHREADS 256
#define NBLK  ((W/TX)*(H/TY)*BATCH)   // 2048

typedef unsigned long long u64;

#define W0 0.00102838f
#define W1 0.00759876f
#define W2 0.03600077f
#define W3 0.10936070f
#define W4 0.21300554f
#define W5 0.26601173f
__device__ __forceinline__ float gwc(int k) {
    const float t[WS] = {W0,W1,W2,W3,W4,W5,W4,W3,W2,W1,W0};
    return t[k];   // fully-unrolled callers -> compile-time constant
}

__device__ float    g_pnum[NBLK];
__device__ float    g_pden[NBLK];
__device__ unsigned g_cnt;

// ---------------- f32x2 packed helpers ----------------
__device__ __forceinline__ u64 pk2(float lo, float hi) {
    u64 r; asm("mov.b64 %0, {%1, %2};" : "=l"(r) : "f"(lo), "f"(hi)); return r;
}
__device__ __forceinline__ float lo2(u64 v) {
    float a, b; asm("mov.b64 {%0, %1}, %2;" : "=f"(a), "=f"(b) : "l"(v)); return a;
}
__device__ __forceinline__ float hi2(u64 v) {
    float a, b; asm("mov.b64 {%0, %1}, %2;" : "=f"(a), "=f"(b) : "l"(v)); return b;
}
__device__ __forceinline__ u64 fma2(u64 a, u64 b, u64 c) {
    u64 d; asm("fma.rn.f32x2 %0, %1, %2, %3;" : "=l"(d) : "l"(a), "l"(b), "l"(c)); return d;
}

extern __shared__ float smem[];

// dynamic smem layout:
//   MQ : TY*PITCH ulonglong2 = 38.4KB
//        .x = (mu1v, mu2v)  packed vertical means
//        .y = (Esumv, E12v) packed vertical (E11+E22, E12)
//   (mask phase reuses this plane as float scratch)
#define SMEM_FLOATS (TY*PITCH*4)
#define SMEM_BYTES  (SMEM_FLOATS * (int)sizeof(float))

// ---------------- pass V: vertical box filter on match (mask scratch) ---------
template<bool CHK>
__device__ __forceinline__ void mask_passV(const float* __restrict__ mp,
                                           int x0, int y0, float* scr, int tid) {
    for (int i = tid; i < XPAD * (TY / 4); i += NTHREADS) {
        int x  = i % XPAD;
        int yb = (i / XPAD) * 4;
        if (x >= TXW) continue;
        int gx = x0 + x - 5;
        float S[4] = {0, 0, 0, 0};
        if (CHK) {
            bool xin = (unsigned)gx < W;
            #pragma unroll
            for (int k = 0; k < WS + 3; k++) {
                int gy = y0 + yb + k - 5;
                float v = (xin && (unsigned)gy < H) ? mp[gy * W + gx] : 0.f;
                #pragma unroll
                for (int r = 0; r < 4; r++) {
                    int kk = k - r;
                    if (kk >= 0 && kk < WS) S[r] += v;
                }
            }
        } else {
            const float* col = mp + (size_t)(y0 + yb - 5) * W + gx;
            #pragma unroll
            for (int k = 0; k < WS + 3; k++) {
                float v = col[k * W];
                #pragma unroll
                for (int r = 0; r < 4; r++) {
                    int kk = k - r;
                    if (kk >= 0 && kk < WS) S[r] += v;
                }
            }
        }
        #pragma unroll
        for (int r = 0; r < 4; r++) scr[(yb + r) * PITCH + x] = S[r];
    }
}

// ---------------- pass V: vertical Gaussian, 2 packed fields (R10 version) ----
template<bool CHK>
__device__ __forceinline__ void chan_passV(const float* __restrict__ p1,
                                           const float* __restrict__ p2,
                                           int x0, int y0,
                                           ulonglong2* MQ, int tid) {
    for (int i = tid; i < XPAD * (TY / 4); i += NTHREADS) {
        int x  = i % XPAD;
        int yb = (i / XPAD) * 4;
        if (x >= TXW) continue;
        int gx = x0 + x - 5;
        bool xin = (unsigned)gx < W;
        const float* c1 = p1 + (size_t)(y0 + yb - 5) * W + gx;
        const float* c2 = p2 + (size_t)(y0 + yb - 5) * W + gx;

        u64 VM[4] = {0,0,0,0};
        u64 VQ[4] = {0,0,0,0};

        #pragma unroll
        for (int k = 0; k < WS + 3; k++) {
            float a, bb;
            if (CHK) {
                int gy = y0 + yb + k - 5;
                bool in = xin && (unsigned)gy < H;
                a  = in ? p1[gy * W + gx] : 0.f;
                bb = in ? p2[gy * W + gx] : 0.f;
            } else {
                a  = c1[k * W];
                bb = c2[k * W];
            }
            u64 v = pk2(a, bb);
            u64 q = pk2(fmaf(bb, bb, a * a), a * bb);
            #pragma unroll
            for (int r = 0; r < 4; r++) {
                int kk = k - r;
                if (kk >= 0 && kk < WS) {
                    float w = gwc(kk);
                    u64 ww = pk2(w, w);
                    VM[r] = fma2(ww, v, VM[r]);
                    VQ[r] = fma2(ww, q, VQ[r]);
                }
            }
        }
        #pragma unroll
        for (int r = 0; r < 4; r++) {
            MQ[(yb + r) * PITCH + x] = make_ulonglong2(VM[r], VQ[r]);  // STS.128
        }
    }
}

__global__ __launch_bounds__(NTHREADS, 5) void ssim_kernel(
    const float* __restrict__ img1,
    const float* __restrict__ img2,
    const float* __restrict__ match,
    float* __restrict__ out)
{
    ulonglong2* MQ  = (ulonglong2*)smem;
    float*      scr = smem;           // mask scratch aliases the MQ plane

    // mask nibbles: one uint8 per (y, x-group-of-4): 32*16 = 512B static smem
    __shared__ unsigned char mask_nib[TY * 16];

    const int tid = threadIdx.x;
    const int x0 = blockIdx.x * TX;
    const int y0 = blockIdx.y * TY;
    const int b  = blockIdx.z;
    const bool interior = (x0 > 0) && (x0 + TX < W) && (y0 > 0) && (y0 + TY < H);

    float lnum = 0.f;
    float lden = 0.f;

    // =================== mask phase (scratch in MQ plane) ===================
    {
        const float* mp = match + (size_t)b * H * W;
        if (interior) mask_passV<false>(mp, x0, y0, scr, tid);
        else          mask_passV<true >(mp, x0, y0, scr, tid);
        __syncthreads();
        #pragma unroll
        for (int ii = 0; ii < 2; ii++) {
            int i  = tid + ii * NTHREADS;
            int y  = i & 31;
            int xg = i >> 5;
            int base = y * PITCH + 4 * xg;
            float tb[WS + 3];
            #pragma unroll
            for (int k = 0; k < WS + 3; k++) tb[k] = scr[base + k];
            float S = 0.f;
            #pragma unroll
            for (int k = 0; k < WS; k++) S += tb[k];
            unsigned nib = 0;
            #pragma unroll
            for (int r = 0; r < 4; r++) {
                if (r > 0) S = S - tb[r - 1] + tb[r + WS - 1];
                float m = S * (1.0f / 121.0f) + 1e-07f;
                bool hit = (m > 0.5f);
                nib |= (hit ? 1u : 0u) << r;
                lden += hit ? (1.0f + 1e-07f) : 1e-07f;
            }
            mask_nib[y * 16 + xg] = (unsigned char)nib;
        }
        __syncthreads();
    }

    // =================== per-channel: pass V then pass H ===================
    for (int c = 0; c < CH; c++) {
        const float* p1 = img1 + ((size_t)b * CH + c) * H * W;
        const float* p2 = img2 + ((size_t)b * CH + c) * H * W;

        if (interior) chan_passV<false>(p1, p2, x0, y0, MQ, tid);
        else          chan_passV<true >(p1, p2, x0, y0, MQ, tid);
        __syncthreads();

        // ---- pass H: horizontal Gaussian + SSIM. lanes = y (conflict-free)
        #pragma unroll
        for (int ii = 0; ii < 2; ii++) {
            int i  = tid + ii * NTHREADS;
            int y  = i & 31;
            int xg = i >> 5;
            int base = y * PITCH + 4 * xg;

            u64 HM[4] = {0,0,0,0};
            u64 HQ[4] = {0,0,0,0};
            #pragma unroll
            for (int k = 0; k < WS + 3; k++) {
                ulonglong2 mq = MQ[base + k];      // one LDS.128
                u64 mk = mq.x;
                u64 qk = mq.y;
                #pragma unroll
                for (int r = 0; r < 4; r++) {
                    int kk = k - r;
                    if (kk >= 0 && kk < WS) {
                        float w = gwc(kk);
                        u64 ww = pk2(w, w);
                        HM[r] = fma2(ww, mk, HM[r]);
                        HQ[r] = fma2(ww, qk, HQ[r]);
                    }
                }
            }
            unsigned nib = mask_nib[y * 16 + xg];
            const float C1 = 1e-4f;
            const float C2 = 9e-4f;
            #pragma unroll
            for (int r = 0; r < 4; r++) {
                float mu1  = lo2(HM[r]);
                float mu2  = hi2(HM[r]);
                float esum = lo2(HQ[r]);
                float e12  = hi2(HQ[r]);
                float mu1sq = mu1 * mu1;
                float mu2sq = mu2 * mu2;
                float mu12  = mu1 * mu2;
                float sden = esum - mu1sq - mu2sq;   // s11 + s22
                float s12  = e12 - mu12;
                float numer = (2.f * mu12 + C1) * (2.f * s12 + C2);
                float denom = (mu1sq + mu2sq + C1) * (sden + C2);
                float ssim = __fdividef(numer, denom);
                float mv = ((nib >> r) & 1u) ? (1.0f + 1e-07f) : 1e-07f;
                lnum += (1.f - ssim) * mv;
            }
        }
        __syncthreads();
    }

    // =================== block reduction + partials + last-block finalize ========
    const unsigned full = 0xffffffffu;
    #pragma unroll
    for (int o = 16; o > 0; o >>= 1) {
        lnum += __shfl_down_sync(full, lnum, o);
        lden += __shfl_down_sync(full, lden, o);
    }
    __shared__ float red[16];
    __shared__ unsigned s_last;
    int wid = tid >> 5, lane = tid & 31;
    if (lane == 0) { red[wid] = lnum; red[wid + 8] = lden; }
    __syncthreads();
    if (tid == 0) {
        float n = 0.f, d = 0.f;
        #pragma unroll
        for (int i = 0; i < 8; i++) { n += red[i]; d += red[i + 8]; }
        int blk = (blockIdx.z * gridDim.y + blockIdx.y) * gridDim.x + blockIdx.x;
        g_pnum[blk] = n;
        g_pden[blk] = d;
        __threadfence();
        unsigned o = atomicAdd(&g_cnt, 1u);
        s_last = (o == NBLK - 1) ? 1u : 0u;
    }
    __syncthreads();

    if (s_last) {
        __threadfence();
        double dn = 0.0, dd = 0.0;
        for (int i = tid; i < NBLK; i += NTHREADS) {
            dn += (double)g_pnum[i];
            dd += (double)g_pden[i];
        }
        #pragma unroll
        for (int o = 16; o > 0; o >>= 1) {
            dn += __shfl_down_sync(full, dn, o);
            dd += __shfl_down_sync(full, dd, o);
        }
        __shared__ double dred[16];
        if (lane == 0) { dred[wid] = dn; dred[wid + 8] = dd; }
        __syncthreads();
        if (tid == 0) {
            double n = 0.0, d = 0.0;
            #pragma unroll
            for (int i = 0; i < 8; i++) { n += dred[i]; d += dred[i + 8]; }
            out[0] = (float)(n / d / 3.0);
            g_cnt = 0;   // reset for next graph replay
        }
    }
}

extern "C" void kernel_launch(void* const* d_in, const int* in_sizes, int n_in,
                              void* d_out, int out_size) {
    const float* img1  = (const float*)d_in[0];
    const float* img2  = (const float*)d_in[1];
    const float* match = (const float*)d_in[2];

    cudaFuncSetAttribute(ssim_kernel,
                         cudaFuncAttributeMaxDynamicSharedMemorySize, SMEM_BYTES);

    dim3 grid(W / TX, H / TY, BATCH);
    ssim_kernel<<<grid, NTHREADS, SMEM_BYTES>>>(img1, img2, match, (float*)d_out);
}

// round 14
// speedup vs baseline: 1.1698x; 1.1476x over previous
#include <cuda_runtime.h>
#include <math.h>

#define BATCH 16
#define CH    3
#define H     512
#define W     512
#define WS    11

#define TX    64
#define TY    32
#define TXW   (TX + 10)     // 74 plane columns
#define XPAD  80            // padded x iteration range for pass V
#define PITCH 75            // odd pitch -> conflict-free LDS
#define NTHREADS 256
#define NBLK  ((W/TX)*(H/TY)*BATCH)   // 2048

typedef unsigned long long u64;

#define W0 0.00102838f
#define W1 0.00759876f
#define W2 0.03600077f
#define W3 0.10936070f
#define W4 0.21300554f
#define W5 0.26601173f
__device__ __forceinline__ float gwc(int k) {
    const float t[WS] = {W0,W1,W2,W3,W4,W5,W4,W3,W2,W1,W0};
    return t[k];   // fully-unrolled callers -> compile-time constant
}

__device__ float    g_pnum[NBLK];
__device__ float    g_pden[NBLK];
__device__ unsigned g_cnt;

// ---------------- f32x2 packed helpers ----------------
__device__ __forceinline__ u64 pk2(float lo, float hi) {
    u64 r; asm("mov.b64 %0, {%1, %2};" : "=l"(r) : "f"(lo), "f"(hi)); return r;
}
__device__ __forceinline__ float lo2(u64 v) {
    float a, b; asm("mov.b64 {%0, %1}, %2;" : "=f"(a), "=f"(b) : "l"(v)); return a;
}
__device__ __forceinline__ float hi2(u64 v) {
    float a, b; asm("mov.b64 {%0, %1}, %2;" : "=f"(a), "=f"(b) : "l"(v)); return b;
}
__device__ __forceinline__ u64 fma2(u64 a, u64 b, u64 c) {
    u64 d; asm("fma.rn.f32x2 %0, %1, %2, %3;" : "=l"(d) : "l"(a), "l"(b), "l"(c)); return d;
}

extern __shared__ float smem[];

// dynamic smem layout:
//   MQ : TY*PITCH ulonglong2 = 38.4KB
//        .x = (mu1v, mu2v)  packed vertical means
//        .y = (Esumv, E12v) packed vertical (E11+E22, E12)
//   (mask phase reuses this plane as float scratch)
#define SMEM_FLOATS (TY*PITCH*4)
#define SMEM_BYTES  (SMEM_FLOATS * (int)sizeof(float))

// ---------------- pass V: vertical box filter on match (mask scratch) ---------
template<bool CHK>
__device__ __forceinline__ void mask_passV(const float* __restrict__ mp,
                                           int x0, int y0, float* scr, int tid) {
    for (int i = tid; i < XPAD * (TY / 4); i += NTHREADS) {
        int x  = i % XPAD;
        int yb = (i / XPAD) * 4;
        if (x >= TXW) continue;
        int gx = x0 + x - 5;
        float S[4] = {0, 0, 0, 0};
        if (CHK) {
            bool xin = (unsigned)gx < W;
            #pragma unroll
            for (int k = 0; k < WS + 3; k++) {
                int gy = y0 + yb + k - 5;
                float v = (xin && (unsigned)gy < H) ? mp[gy * W + gx] : 0.f;
                #pragma unroll
                for (int r = 0; r < 4; r++) {
                    int kk = k - r;
                    if (kk >= 0 && kk < WS) S[r] += v;
                }
            }
        } else {
            const float* col = mp + (size_t)(y0 + yb - 5) * W + gx;
            #pragma unroll
            for (int k = 0; k < WS + 3; k++) {
                float v = col[k * W];
                #pragma unroll
                for (int r = 0; r < 4; r++) {
                    int kk = k - r;
                    if (kk >= 0 && kk < WS) S[r] += v;
                }
            }
        }
        #pragma unroll
        for (int r = 0; r < 4; r++) scr[(yb + r) * PITCH + x] = S[r];
    }
}

// ---------------- pass V: vertical Gaussian, 2 packed fields (R10 version) ----
template<bool CHK>
__device__ __forceinline__ void chan_passV(const float* __restrict__ p1,
                                           const float* __restrict__ p2,
                                           int x0, int y0,
                                           ulonglong2* MQ, int tid) {
    for (int i = tid; i < XPAD * (TY / 4); i += NTHREADS) {
        int x  = i % XPAD;
        int yb = (i / XPAD) * 4;
        if (x >= TXW) continue;
        int gx = x0 + x - 5;
        bool xin = (unsigned)gx < W;
        const float* c1 = p1 + (size_t)(y0 + yb - 5) * W + gx;
        const float* c2 = p2 + (size_t)(y0 + yb - 5) * W + gx;

        u64 VM[4] = {0,0,0,0};
        u64 VQ[4] = {0,0,0,0};

        #pragma unroll
        for (int k = 0; k < WS + 3; k++) {
            float a, bb;
            if (CHK) {
                int gy = y0 + yb + k - 5;
                bool in = xin && (unsigned)gy < H;
                a  = in ? p1[gy * W + gx] : 0.f;
                bb = in ? p2[gy * W + gx] : 0.f;
            } else {
                a  = c1[k * W];
                bb = c2[k * W];
            }
            u64 v = pk2(a, bb);
            u64 q = pk2(fmaf(bb, bb, a * a), a * bb);
            #pragma unroll
            for (int r = 0; r < 4; r++) {
                int kk = k - r;
                if (kk >= 0 && kk < WS) {
                    float w = gwc(kk);
                    u64 ww = pk2(w, w);
                    VM[r] = fma2(ww, v, VM[r]);
                    VQ[r] = fma2(ww, q, VQ[r]);
                }
            }
        }
        #pragma unroll
        for (int r = 0; r < 4; r++) {
            MQ[(yb + r) * PITCH + x] = make_ulonglong2(VM[r], VQ[r]);  // STS.128
        }
    }
}

__global__ __launch_bounds__(NTHREADS, 4) void ssim_kernel(
    const float* __restrict__ img1,
    const float* __restrict__ img2,
    const float* __restrict__ match,
    float* __restrict__ out)
{
    ulonglong2* MQ  = (ulonglong2*)smem;
    float*      scr = smem;           // mask scratch aliases the MQ plane

    // mask bits: one uint8 per (y, x-group-of-8): 32*8 = 256B static smem
    __shared__ unsigned char mask_byte[TY * 8];

    const int tid = threadIdx.x;
    const int x0 = blockIdx.x * TX;
    const int y0 = blockIdx.y * TY;
    const int b  = blockIdx.z;
    const bool interior = (x0 > 0) && (x0 + TX < W) && (y0 > 0) && (y0 + TY < H);

    // H-pass item mapping: one item per thread, 8 outputs along x
    const int hy   = tid & 31;        // y row
    const int hxg  = tid >> 5;        // x-group of 8 (0..7)
    const int hbase = hy * PITCH + 8 * hxg;

    float lnum = 0.f;
    float lden = 0.f;

    // =================== mask phase (scratch in MQ plane) ===================
    {
        const float* mp = match + (size_t)b * H * W;
        if (interior) mask_passV<false>(mp, x0, y0, scr, tid);
        else          mask_passV<true >(mp, x0, y0, scr, tid);
        __syncthreads();
        {
            float tb[WS + 7];
            #pragma unroll
            for (int k = 0; k < WS + 7; k++) tb[k] = scr[hbase + k];
            float S = 0.f;
            #pragma unroll
            for (int k = 0; k < WS; k++) S += tb[k];
            unsigned bits = 0;
            #pragma unroll
            for (int r = 0; r < 8; r++) {
                if (r > 0) S = S - tb[r - 1] + tb[r + WS - 1];
                float m = S * (1.0f / 121.0f) + 1e-07f;
                bool hit = (m > 0.5f);
                bits |= (hit ? 1u : 0u) << r;
                lden += hit ? (1.0f + 1e-07f) : 1e-07f;
            }
            mask_byte[hy * 8 + hxg] = (unsigned char)bits;
        }
        __syncthreads();
    }

    // =================== per-channel: pass V then pass H ===================
    for (int c = 0; c < CH; c++) {
        const float* p1 = img1 + ((size_t)b * CH + c) * H * W;
        const float* p2 = img2 + ((size_t)b * CH + c) * H * W;

        if (interior) chan_passV<false>(p1, p2, x0, y0, MQ, tid);
        else          chan_passV<true >(p1, p2, x0, y0, MQ, tid);
        __syncthreads();

        // ---- pass H: horizontal Gaussian + SSIM, 8 outputs/thread
        {
            u64 HM[8] = {0,0,0,0,0,0,0,0};
            u64 HQ[8] = {0,0,0,0,0,0,0,0};
            #pragma unroll
            for (int k = 0; k < WS + 7; k++) {    // 18-wide window serves 8 outputs
                ulonglong2 mq = MQ[hbase + k];    // one LDS.128
                u64 mk = mq.x;
                u64 qk = mq.y;
                #pragma unroll
                for (int r = 0; r < 8; r++) {
                    int kk = k - r;
                    if (kk >= 0 && kk < WS) {
                        float w = gwc(kk);
                        u64 ww = pk2(w, w);
                        HM[r] = fma2(ww, mk, HM[r]);
                        HQ[r] = fma2(ww, qk, HQ[r]);
                    }
                }
            }
            unsigned bits = mask_byte[hy * 8 + hxg];
            const float C1 = 1e-4f;
            const float C2 = 9e-4f;
            #pragma unroll
            for (int r = 0; r < 8; r++) {
                float mu1  = lo2(HM[r]);
                float mu2  = hi2(HM[r]);
                float esum = lo2(HQ[r]);
                float e12  = hi2(HQ[r]);
                float mu1sq = mu1 * mu1;
                float mu2sq = mu2 * mu2;
                float mu12  = mu1 * mu2;
                float sden = esum - mu1sq - mu2sq;   // s11 + s22
                float s12  = e12 - mu12;
                float numer = (2.f * mu12 + C1) * (2.f * s12 + C2);
                float denom = (mu1sq + mu2sq + C1) * (sden + C2);
                float ssim = __fdividef(numer, denom);
                float mv = ((bits >> r) & 1u) ? (1.0f + 1e-07f) : 1e-07f;
                lnum += (1.f - ssim) * mv;
            }
        }
        __syncthreads();
    }

    // =================== block reduction + partials + last-block finalize ========
    const unsigned full = 0xffffffffu;
    #pragma unroll
    for (int o = 16; o > 0; o >>= 1) {
        lnum += __shfl_down_sync(full, lnum, o);
        lden += __shfl_down_sync(full, lden, o);
    }
    __shared__ float red[16];
    __shared__ unsigned s_last;
    int wid = tid >> 5, lane = tid & 31;
    if (lane == 0) { red[wid] = lnum; red[wid + 8] = lden; }
    __syncthreads();
    if (tid == 0) {
        float n = 0.f, d = 0.f;
        #pragma unroll
        for (int i = 0; i < 8; i++) { n += red[i]; d += red[i + 8]; }
        int blk = (blockIdx.z * gridDim.y + blockIdx.y) * gridDim.x + blockIdx.x;
        g_pnum[blk] = n;
        g_pden[blk] = d;
        __threadfence();
        unsigned o = atomicAdd(&g_cnt, 1u);
        s_last = (o == NBLK - 1) ? 1u : 0u;
    }
    __syncthreads();

    if (s_last) {
        __threadfence();
        double dn = 0.0, dd = 0.0;
        for (int i = tid; i < NBLK; i += NTHREADS) {
            dn += (double)g_pnum[i];
            dd += (double)g_pden[i];
        }
        #pragma unroll
        for (int o = 16; o > 0; o >>= 1) {
            dn += __shfl_down_sync(full, dn, o);
            dd += __shfl_down_sync(full, dd, o);
        }
        __shared__ double dred[16];
        if (lane == 0) { dred[wid] = dn; dred[wid + 8] = dd; }
        __syncthreads();
        if (tid == 0) {
            double n = 0.0, d = 0.0;
            #pragma unroll
            for (int i = 0; i < 8; i++) { n += dred[i]; d += dred[i + 8]; }
            out[0] = (float)(n / d / 3.0);
            g_cnt = 0;   // reset for next graph replay
        }
    }
}

extern "C" void kernel_launch(void* const* d_in, const int* in_sizes, int n_in,
                              void* d_out, int out_size) {
    const float* img1  = (const float*)d_in[0];
    const float* img2  = (const float*)d_in[1];
    const float* match = (const float*)d_in[2];

    cudaFuncSetAttribute(ssim_kernel,
                         cudaFuncAttributeMaxDynamicSharedMemorySize, SMEM_BYTES);

    dim3 grid(W / TX, H / TY, BATCH);
    ssim_kernel<<<grid, NTHREADS, SMEM_BYTES>>>(img1, img2, match, (float*)d_out);
}

// round 15
// speedup vs baseline: 1.1769x; 1.0061x over previous
#include <cuda_runtime.h>
#include <math.h>

#define BATCH 16
#define CH    3
#define H     512
#define W     512
#define WS    11

#define TX    64
#define TY    32
#define TXW   (TX + 10)     // 74 plane columns
#define XPAD  80            // padded x iteration range for y4 (edge) pass V
#define PITCH 75            // odd pitch -> conflict-free LDS
#define NTHREADS 256
#define NBLK  ((W/TX)*(H/TY)*BATCH)   // 2048

typedef unsigned long long u64;

#define W0 0.00102838f
#define W1 0.00759876f
#define W2 0.03600077f
#define W3 0.10936070f
#define W4 0.21300554f
#define W5 0.26601173f
__device__ __forceinline__ float gwc(int k) {
    const float t[WS] = {W0,W1,W2,W3,W4,W5,W4,W3,W2,W1,W0};
    return t[k];   // fully-unrolled callers -> compile-time constant
}

__device__ float    g_pnum[NBLK];
__device__ float    g_pden[NBLK];
__device__ unsigned g_cnt;

// ---------------- f32x2 packed helpers ----------------
__device__ __forceinline__ u64 pk2(float lo, float hi) {
    u64 r; asm("mov.b64 %0, {%1, %2};" : "=l"(r) : "f"(lo), "f"(hi)); return r;
}
__device__ __forceinline__ float lo2(u64 v) {
    float a, b; asm("mov.b64 {%0, %1}, %2;" : "=f"(a), "=f"(b) : "l"(v)); return a;
}
__device__ __forceinline__ float hi2(u64 v) {
    float a, b; asm("mov.b64 {%0, %1}, %2;" : "=f"(a), "=f"(b) : "l"(v)); return b;
}
__device__ __forceinline__ u64 fma2(u64 a, u64 b, u64 c) {
    u64 d; asm("fma.rn.f32x2 %0, %1, %2, %3;" : "=l"(d) : "l"(a), "l"(b), "l"(c)); return d;
}

extern __shared__ float smem[];

// dynamic smem layout:
//   MQ : TY*PITCH ulonglong2 = 38.4KB
//        .x = (mu1v, mu2v)  packed vertical means
//        .y = (Esumv, E12v) packed vertical (E11+E22, E12)
//   (mask phase reuses this plane as float scratch)
#define SMEM_FLOATS (TY*PITCH*4)
#define SMEM_BYTES  (SMEM_FLOATS * (int)sizeof(float))

// ---------------- pass V: vertical box filter on match (mask scratch) ---------
template<bool CHK>
__device__ __forceinline__ void mask_passV(const float* __restrict__ mp,
                                           int x0, int y0, float* scr, int tid) {
    for (int i = tid; i < XPAD * (TY / 4); i += NTHREADS) {
        int x  = i % XPAD;
        int yb = (i / XPAD) * 4;
        if (x >= TXW) continue;
        int gx = x0 + x - 5;
        float S[4] = {0, 0, 0, 0};
        if (CHK) {
            bool xin = (unsigned)gx < W;
            #pragma unroll
            for (int k = 0; k < WS + 3; k++) {
                int gy = y0 + yb + k - 5;
                float v = (xin && (unsigned)gy < H) ? mp[gy * W + gx] : 0.f;
                #pragma unroll
                for (int r = 0; r < 4; r++) {
                    int kk = k - r;
                    if (kk >= 0 && kk < WS) S[r] += v;
                }
            }
        } else {
            const float* col = mp + (size_t)(y0 + yb - 5) * W + gx;
            #pragma unroll
            for (int k = 0; k < WS + 3; k++) {
                float v = col[k * W];
                #pragma unroll
                for (int r = 0; r < 4; r++) {
                    int kk = k - r;
                    if (kk >= 0 && kk < WS) S[r] += v;
                }
            }
        }
        #pragma unroll
        for (int r = 0; r < 4; r++) scr[(yb + r) * PITCH + x] = S[r];
    }
}

// ---------------- pass V (edge blocks): y4, bounds-checked ---------------------
__device__ __forceinline__ void chan_passV_edge(const float* __restrict__ p1,
                                                const float* __restrict__ p2,
                                                int x0, int y0,
                                                ulonglong2* MQ, int tid) {
    for (int i = tid; i < XPAD * (TY / 4); i += NTHREADS) {
        int x  = i % XPAD;
        int yb = (i / XPAD) * 4;
        if (x >= TXW) continue;
        int gx = x0 + x - 5;
        bool xin = (unsigned)gx < W;

        u64 VM[4] = {0,0,0,0};
        u64 VQ[4] = {0,0,0,0};

        #pragma unroll
        for (int k = 0; k < WS + 3; k++) {
            int gy = y0 + yb + k - 5;
            bool in = xin && (unsigned)gy < H;
            float a  = in ? p1[gy * W + gx] : 0.f;
            float bb = in ? p2[gy * W + gx] : 0.f;
            u64 v = pk2(a, bb);
            u64 q = pk2(fmaf(bb, bb, a * a), a * bb);
            #pragma unroll
            for (int r = 0; r < 4; r++) {
                int kk = k - r;
                if (kk >= 0 && kk < WS) {
                    float w = gwc(kk);
                    u64 ww = pk2(w, w);
                    VM[r] = fma2(ww, v, VM[r]);
                    VQ[r] = fma2(ww, q, VQ[r]);
                }
            }
        }
        #pragma unroll
        for (int r = 0; r < 4; r++) {
            MQ[(yb + r) * PITCH + x] = make_ulonglong2(VM[r], VQ[r]);
        }
    }
}

// ---------------- pass V (interior blocks): y8 blocking, 18-row window ---------
__device__ __forceinline__ void chan_passV_int(const float* __restrict__ p1,
                                               const float* __restrict__ p2,
                                               int x0, int y0,
                                               ulonglong2* MQ, int tid) {
    for (int i = tid; i < TXW * (TY / 8); i += NTHREADS) {   // 296 items
        int strip = i / TXW;
        int x  = i - strip * TXW;
        int yb = strip * 8;
        int gx = x0 + x - 5;
        const float* c1 = p1 + (size_t)(y0 + yb - 5) * W + gx;
        const float* c2 = p2 + (size_t)(y0 + yb - 5) * W + gx;

        u64 VM[8] = {0,0,0,0,0,0,0,0};
        u64 VQ[8] = {0,0,0,0,0,0,0,0};

        #pragma unroll
        for (int k = 0; k < WS + 7; k++) {        // 18 rows serve 8 outputs
            float a  = c1[k * W];
            float bb = c2[k * W];
            u64 v = pk2(a, bb);
            u64 q = pk2(fmaf(bb, bb, a * a), a * bb);
            #pragma unroll
            for (int r = 0; r < 8; r++) {
                int kk = k - r;
                if (kk >= 0 && kk < WS) {
                    float w = gwc(kk);
                    u64 ww = pk2(w, w);
                    VM[r] = fma2(ww, v, VM[r]);
                    VQ[r] = fma2(ww, q, VQ[r]);
                }
            }
        }
        #pragma unroll
        for (int r = 0; r < 8; r++) {
            MQ[(yb + r) * PITCH + x] = make_ulonglong2(VM[r], VQ[r]);  // STS.128
        }
    }
}

__global__ __launch_bounds__(NTHREADS, 4) void ssim_kernel(
    const float* __restrict__ img1,
    const float* __restrict__ img2,
    const float* __restrict__ match,
    float* __restrict__ out)
{
    ulonglong2* MQ  = (ulonglong2*)smem;
    float*      scr = smem;           // mask scratch aliases the MQ plane

    // mask bits: one uint8 per (y, x-group-of-8): 32*8 = 256B static smem
    __shared__ unsigned char mask_byte[TY * 8];

    const int tid = threadIdx.x;
    const int x0 = blockIdx.x * TX;
    const int y0 = blockIdx.y * TY;
    const int b  = blockIdx.z;
    const bool interior = (x0 > 0) && (x0 + TX < W) && (y0 > 0) && (y0 + TY < H);

    // H-pass item mapping: one item per thread, 8 outputs along x
    const int hy   = tid & 31;        // y row
    const int hxg  = tid >> 5;        // x-group of 8 (0..7)
    const int hbase = hy * PITCH + 8 * hxg;

    float lnum = 0.f;
    float lden = 0.f;

    // =================== mask phase (scratch in MQ plane) ===================
    {
        const float* mp = match + (size_t)b * H * W;
        if (interior) mask_passV<false>(mp, x0, y0, scr, tid);
        else          mask_passV<true >(mp, x0, y0, scr, tid);
        __syncthreads();
        {
            float tb[WS + 7];
            #pragma unroll
            for (int k = 0; k < WS + 7; k++) tb[k] = scr[hbase + k];
            float S = 0.f;
            #pragma unroll
            for (int k = 0; k < WS; k++) S += tb[k];
            unsigned bits = 0;
            #pragma unroll
            for (int r = 0; r < 8; r++) {
                if (r > 0) S = S - tb[r - 1] + tb[r + WS - 1];
                float m = S * (1.0f / 121.0f) + 1e-07f;
                bool hit = (m > 0.5f);
                bits |= (hit ? 1u : 0u) << r;
                lden += hit ? (1.0f + 1e-07f) : 1e-07f;
            }
            mask_byte[hy * 8 + hxg] = (unsigned char)bits;
        }
        __syncthreads();
    }

    // =================== per-channel: pass V then pass H ===================
    for (int c = 0; c < CH; c++) {
        const float* p1 = img1 + ((size_t)b * CH + c) * H * W;
        const float* p2 = img2 + ((size_t)b * CH + c) * H * W;

        if (interior) chan_passV_int (p1, p2, x0, y0, MQ, tid);
        else          chan_passV_edge(p1, p2, x0, y0, MQ, tid);
        __syncthreads();

        // ---- pass H: horizontal Gaussian + SSIM, 8 outputs/thread
        {
            u64 HM[8] = {0,0,0,0,0,0,0,0};
            u64 HQ[8] = {0,0,0,0,0,0,0,0};
            #pragma unroll
            for (int k = 0; k < WS + 7; k++) {    // 18-wide window serves 8 outputs
                ulonglong2 mq = MQ[hbase + k];    // one LDS.128
                u64 mk = mq.x;
                u64 qk = mq.y;
                #pragma unroll
                for (int r = 0; r < 8; r++) {
                    int kk = k - r;
                    if (kk >= 0 && kk < WS) {
                        float w = gwc(kk);
                        u64 ww = pk2(w, w);
                        HM[r] = fma2(ww, mk, HM[r]);
                        HQ[r] = fma2(ww, qk, HQ[r]);
                    }
                }
            }
            unsigned bits = mask_byte[hy * 8 + hxg];
            const float C1 = 1e-4f;
            const float C2 = 9e-4f;
            #pragma unroll
            for (int r = 0; r < 8; r++) {
                float mu1  = lo2(HM[r]);
                float mu2  = hi2(HM[r]);
                float esum = lo2(HQ[r]);
                float e12  = hi2(HQ[r]);
                float mu1sq = mu1 * mu1;
                float mu2sq = mu2 * mu2;
                float mu12  = mu1 * mu2;
                float sden = esum - mu1sq - mu2sq;   // s11 + s22
                float s12  = e12 - mu12;
                float numer = (2.f * mu12 + C1) * (2.f * s12 + C2);
                float denom = (mu1sq + mu2sq + C1) * (sden + C2);
                float ssim = __fdividef(numer, denom);
                float mv = ((bits >> r) & 1u) ? (1.0f + 1e-07f) : 1e-07f;
                lnum += (1.f - ssim) * mv;
            }
        }
        __syncthreads();
    }

    // =================== block reduction + partials + last-block finalize ========
    const unsigned full = 0xffffffffu;
    #pragma unroll
    for (int o = 16; o > 0; o >>= 1) {
        lnum += __shfl_down_sync(full, lnum, o);
        lden += __shfl_down_sync(full, lden, o);
    }
    __shared__ float red[16];
    __shared__ unsigned s_last;
    int wid = tid >> 5, lane = tid & 31;
    if (lane == 0) { red[wid] = lnum; red[wid + 8] = lden; }
    __syncthreads();
    if (tid == 0) {
        float n = 0.f, d = 0.f;
        #pragma unroll
        for (int i = 0; i < 8; i++) { n += red[i]; d += red[i + 8]; }
        int blk = (blockIdx.z * gridDim.y + blockIdx.y) * gridDim.x + blockIdx.x;
        g_pnum[blk] = n;
        g_pden[blk] = d;
        __threadfence();
        unsigned o = atomicAdd(&g_cnt, 1u);
        s_last = (o == NBLK - 1) ? 1u : 0u;
    }
    __syncthreads();

    if (s_last) {
        __threadfence();
        double dn = 0.0, dd = 0.0;
        for (int i = tid; i < NBLK; i += NTHREADS) {
            dn += (double)g_pnum[i];
            dd += (double)g_pden[i];
        }
        #pragma unroll
        for (int o = 16; o > 0; o >>= 1) {
            dn += __shfl_down_sync(full, dn, o);
            dd += __shfl_down_sync(full, dd, o);
        }
        __shared__ double dred[16];
        if (lane == 0) { dred[wid] = dn; dred[wid + 8] = dd; }
        __syncthreads();
        if (tid == 0) {
            double n = 0.0, d = 0.0;
            #pragma unroll
            for (int i = 0; i < 8; i++) { n += dred[i]; d += dred[i + 8]; }
            out[0] = (float)(n / d / 3.0);
            g_cnt = 0;   // reset for next graph replay
        }
    }
}

extern "C" void kernel_launch(void* const* d_in, const int* in_sizes, int n_in,
                              void* d_out, int out_size) {
    const float* img1  = (const float*)d_in[0];
    const float* img2  = (const float*)d_in[1];
    const float* match = (const float*)d_in[2];

    cudaFuncSetAttribute(ssim_kernel,
                         cudaFuncAttributeMaxDynamicSharedMemorySize, SMEM_BYTES);

    dim3 grid(W / TX, H / TY, BATCH);
    ssim_kernel<<<grid, NTHREADS, SMEM_BYTES>>>(img1, img2, match, (float*)d_out);
}